// round 8
// baseline (speedup 1.0000x reference)
#include <cuda_runtime.h>
#include <cuda_bf16.h>
#include <math.h>

// ---------------- constants ----------------
#define BB 16          // batch
#define HH 1024
#define WW 1024
#define PS 16
#define IPS 4
#define CS 4
#define KK 16          // top-k patches
#define DD 256         // model dim
#define NH 4
#define DH 64
#define DFF 1024
#define NL 2
#define NW_ 64         // patches per row = 1024/16
#define NPATCH 4096    // 64*64
#define SEQ 256        // tokens per batch = K*16
#define NTOK 4096      // B*SEQ

// output layout (f32 element offsets, tuple concatenated flat)
#define LEN_COARSE (BB*256*256)              // 1048576
#define OFF_COARSE 0
#define OFF_PATCH  (OFF_COARSE + LEN_COARSE)
#define LEN_PATCH  (BB*KK*PS*PS)             // 65536
#define OFF_PLAB   (OFF_PATCH + LEN_PATCH)
#define OFF_COORD  (OFF_PLAB + LEN_PATCH)
#define LEN_COORD  (BB*KK*2)                 // 512
#define OFF_PLOG   (OFF_COORD + LEN_COORD)
#define OFF_FINAL  (OFF_PLOG + LEN_PATCH)

// ---------------- scratch (static device globals; no allocation) ----------------
__device__ float g_scores[BB * NPATCH];
__device__ int   g_idx[BB * KK];
__device__ int   g_map[BB * NPATCH];
__device__ float g_X   [NTOK * DD];      // tokens
__device__ float g_QKV [NTOK * 3 * DD];  // qkv
__device__ float g_T1  [NTOK * DFF];     // ff hidden / proj / head gelu
__device__ float g_T2  [NTOK * DD];      // attn concat / ff out / head ln
__device__ float g_logits[NTOK];

__device__ __forceinline__ float gelu_exact(float v) {
    return 0.5f * v * (1.0f + erff(v * 0.70710678118654752f));
}

// ---------------- 1) coarse = avgpool4x4(labels) -> out ----------------
__global__ void k_coarse(const float* __restrict__ labels, float* __restrict__ out_coarse) {
    int idx = blockIdx.x * blockDim.x + threadIdx.x;   // B*256*256
    int b  = idx >> 16;
    int yc = (idx >> 8) & 255;
    int xc = idx & 255;
    const float* lp = labels + b * (HH * WW) + (yc * 4) * WW + xc * 4;
    float s = 0.f;
#pragma unroll
    for (int dy = 0; dy < 4; dy++)
#pragma unroll
        for (int dx = 0; dx < 4; dx++) s += lp[dy * WW + dx];
    out_coarse[idx] = s * 0.0625f;
}

// ---------------- 2) per-patch score = avgpool4x4(coarse) ----------------
__global__ void k_scores(const float* __restrict__ coarse) {
    int idx = blockIdx.x * blockDim.x + threadIdx.x;   // B*4096
    int b = idx >> 12;
    int p = idx & 4095;
    int hi = p >> 6, wi = p & 63;
    const float* cp = coarse + b * 65536 + (hi * 4) * 256 + wi * 4;
    float s = 0.f;
#pragma unroll
    for (int dy = 0; dy < 4; dy++)
#pragma unroll
        for (int dx = 0; dx < 4; dx++) s += cp[dy * 256 + dx];
    g_scores[idx] = s * 0.0625f;
}

// ---------------- 3) map init ----------------
__global__ void k_mapinit() {
    int idx = blockIdx.x * blockDim.x + threadIdx.x;
    if (idx < BB * NPATCH) g_map[idx] = -1;
}

// ---------------- 4) top-K per batch (descending, lower index on ties) ----------------
__global__ void k_topk() {
    int b = blockIdx.x;
    __shared__ float sv[NPATCH];
    __shared__ float rv[256];
    __shared__ int   ri[256];
    for (int i = threadIdx.x; i < NPATCH; i += 256) sv[i] = g_scores[b * NPATCH + i];
    __syncthreads();
    for (int it = 0; it < KK; it++) {
        float best = -3.0e38f; int bi = NPATCH;
        for (int i = threadIdx.x; i < NPATCH; i += 256) {
            float v = sv[i];
            if (v > best) { best = v; bi = i; }   // ascending scan keeps lowest idx on ties
        }
        rv[threadIdx.x] = best; ri[threadIdx.x] = bi;
        __syncthreads();
        for (int s = 128; s > 0; s >>= 1) {
            if (threadIdx.x < s) {
                float v2 = rv[threadIdx.x + s]; int i2 = ri[threadIdx.x + s];
                if (v2 > rv[threadIdx.x] || (v2 == rv[threadIdx.x] && i2 < ri[threadIdx.x])) {
                    rv[threadIdx.x] = v2; ri[threadIdx.x] = i2;
                }
            }
            __syncthreads();
        }
        if (threadIdx.x == 0) { g_idx[b * KK + it] = ri[0]; sv[ri[0]] = -3.0e38f; }
        __syncthreads();
    }
}

// ---------------- 5) gather patches / labels / coords / map ----------------
__global__ void k_gather(const float* __restrict__ image, const float* __restrict__ labels,
                         float* __restrict__ out_p, float* __restrict__ out_l,
                         float* __restrict__ out_c) {
    int bk = blockIdx.x;            // 0..255
    int b = bk >> 4, k = bk & 15;
    int pidx = g_idx[bk];
    int hi = pidx >> 6, wi = pidx & 63;
    int t = threadIdx.x;
    int py = t >> 4, px = t & 15;
    int base = b * (HH * WW) + (hi * 16 + py) * WW + wi * 16 + px;
    out_p[bk * 256 + t] = image[base];
    out_l[bk * 256 + t] = labels[base];
    if (t == 0) {
        out_c[bk * 2 + 0] = (float)(hi * 16);
        out_c[bk * 2 + 1] = (float)(wi * 16);
        g_map[b * NPATCH + pidx] = k;
    }
}

// ---------------- 6) patch embed: tokens = conv4x4(pe_w) + pe_b + pos ----------------
__global__ void k_embed(const float* __restrict__ patches, const float* __restrict__ pe_w,
                        const float* __restrict__ pe_b, const float* __restrict__ pos) {
    int n = blockIdx.x;             // token 0..4095
    int d = threadIdx.x;            // 0..255
    int r = n & 255;
    int b = n >> 8;
    int k = r >> 4, q = r & 15;
    int i = q >> 2, j = q & 3;
    __shared__ float sub[16];
    if (d < 16) {
        int a = d >> 2, bb = d & 3;
        sub[d] = patches[(b * 16 + k) * 256 + (i * 4 + a) * 16 + (j * 4 + bb)];
    }
    __syncthreads();
    float s = pe_b[d] + pos[q * DD + d];
#pragma unroll
    for (int p = 0; p < 16; p++) s += __ldg(&pe_w[d * 16 + p]) * sub[p];
    g_X[n * DD + d] = s;
}

// ---------------- 7) SGEMM: C[M,N] = act(A[M,K] * W[N,K]^T + bias) ----------------
// 64x64 tile, BK=16, 256 threads, 4x4 per thread
__global__ __launch_bounds__(256) void k_sgemm(const float* __restrict__ A,
                                               const float* __restrict__ W,
                                               const float* __restrict__ bias,
                                               float* __restrict__ C,
                                               int M, int N, int Kd, int act) {
    __shared__ float As[16][68];
    __shared__ float Bs[16][68];
    int n0 = blockIdx.x * 64;
    int m0 = blockIdx.y * 64;
    int t = threadIdx.x;
    int tx = t & 15, ty = t >> 4;
    int lrow = t >> 2;
    int lk = (t & 3) * 4;
    float acc[4][4];
#pragma unroll
    for (int i = 0; i < 4; i++)
#pragma unroll
        for (int j = 0; j < 4; j++) acc[i][j] = 0.f;

    const float* Ap = A + (m0 + lrow) * Kd + lk;
    const float* Wp = W + (n0 + lrow) * Kd + lk;

    for (int k0 = 0; k0 < Kd; k0 += 16) {
        float4 a4 = *(const float4*)(Ap + k0);
        float4 b4 = *(const float4*)(Wp + k0);
        __syncthreads();
        As[lk + 0][lrow] = a4.x; As[lk + 1][lrow] = a4.y;
        As[lk + 2][lrow] = a4.z; As[lk + 3][lrow] = a4.w;
        Bs[lk + 0][lrow] = b4.x; Bs[lk + 1][lrow] = b4.y;
        Bs[lk + 2][lrow] = b4.z; Bs[lk + 3][lrow] = b4.w;
        __syncthreads();
#pragma unroll
        for (int kk = 0; kk < 16; kk++) {
            float4 av = *(const float4*)&As[kk][ty * 4];
            float4 bv = *(const float4*)&Bs[kk][tx * 4];
            float ar[4] = {av.x, av.y, av.z, av.w};
            float br[4] = {bv.x, bv.y, bv.z, bv.w};
#pragma unroll
            for (int i = 0; i < 4; i++)
#pragma unroll
                for (int j = 0; j < 4; j++) acc[i][j] = fmaf(ar[i], br[j], acc[i][j]);
        }
    }
#pragma unroll
    for (int i = 0; i < 4; i++) {
        int m = m0 + ty * 4 + i;
#pragma unroll
        for (int j = 0; j < 4; j++) {
            int n = n0 + tx * 4 + j;
            float v = acc[i][j] + bias[n];
            if (act) v = gelu_exact(v);
            C[m * N + n] = v;
        }
    }
}

// ---------------- 8) attention: one block per (b,h), flash-style ----------------
__global__ __launch_bounds__(256, 1) void k_attn(const float* __restrict__ QKV,
                                                 float* __restrict__ O) {
    int b = blockIdx.x >> 2;
    int h = blockIdx.x & 3;
    __shared__ float Ks[64 * 64];
    __shared__ float Vs[64 * 64];
    int q = threadIdx.x;            // query token 0..255

    float qreg[64];
    {
        const float4* qp = (const float4*)(QKV + ((b * SEQ + q) * 3 * DD) + h * DH);
#pragma unroll
        for (int d4 = 0; d4 < 16; d4++) {
            float4 v = qp[d4];
            qreg[d4 * 4 + 0] = v.x * 0.125f;
            qreg[d4 * 4 + 1] = v.y * 0.125f;
            qreg[d4 * 4 + 2] = v.z * 0.125f;
            qreg[d4 * 4 + 3] = v.w * 0.125f;
        }
    }
    float o[64];
#pragma unroll
    for (int d = 0; d < 64; d++) o[d] = 0.f;
    float m = -3.0e38f, l = 0.f;

    for (int tile = 0; tile < 4; tile++) {
        __syncthreads();
        for (int i = threadIdx.x; i < 4096; i += 256) {
            int tok = i >> 6, d = i & 63;
            int gbase = (b * SEQ + tile * 64 + tok) * 3 * DD + h * DH + d;
            Ks[i] = QKV[gbase + DD];
            Vs[i] = QKV[gbase + 2 * DD];
        }
        __syncthreads();
#pragma unroll 2
        for (int j = 0; j < 64; j++) {
            const float4* kp = (const float4*)&Ks[j * 64];
            float s = 0.f;
#pragma unroll
            for (int d4 = 0; d4 < 16; d4++) {
                float4 kv = kp[d4];
                s = fmaf(qreg[d4 * 4 + 0], kv.x, s);
                s = fmaf(qreg[d4 * 4 + 1], kv.y, s);
                s = fmaf(qreg[d4 * 4 + 2], kv.z, s);
                s = fmaf(qreg[d4 * 4 + 3], kv.w, s);
            }
            float mn = fmaxf(m, s);
            float c = expf(m - mn);
            float p = expf(s - mn);
            l = l * c + p;
            const float4* vp = (const float4*)&Vs[j * 64];
#pragma unroll
            for (int d4 = 0; d4 < 16; d4++) {
                float4 vv = vp[d4];
                o[d4 * 4 + 0] = fmaf(o[d4 * 4 + 0], c, p * vv.x);
                o[d4 * 4 + 1] = fmaf(o[d4 * 4 + 1], c, p * vv.y);
                o[d4 * 4 + 2] = fmaf(o[d4 * 4 + 2], c, p * vv.z);
                o[d4 * 4 + 3] = fmaf(o[d4 * 4 + 3], c, p * vv.w);
            }
            m = mn;
        }
    }
    float inv = 1.f / l;
    float4* op = (float4*)(O + (b * SEQ + q) * DD + h * DH);
#pragma unroll
    for (int d4 = 0; d4 < 16; d4++) {
        float4 v;
        v.x = o[d4 * 4 + 0] * inv; v.y = o[d4 * 4 + 1] * inv;
        v.z = o[d4 * 4 + 2] * inv; v.w = o[d4 * 4 + 3] * inv;
        op[d4] = v;
    }
}

// ---------------- 9) layernorm (optional residual), row = one block ----------------
__global__ void k_ln(const float* __restrict__ X, const float* __restrict__ R,
                     const float* __restrict__ s, const float* __restrict__ bb,
                     float* __restrict__ Y, int hasRes) {
    int row = blockIdx.x;
    int t = threadIdx.x;
    __shared__ float red[256];
    float x = X[row * DD + t];
    if (hasRes) x += R[row * DD + t];
    red[t] = x;
    __syncthreads();
    for (int sdt = 128; sdt > 0; sdt >>= 1) {
        if (t < sdt) red[t] += red[t + sdt];
        __syncthreads();
    }
    float mean = red[0] * (1.0f / DD);
    __syncthreads();
    float d = x - mean;
    red[t] = d * d;
    __syncthreads();
    for (int sdt = 128; sdt > 0; sdt >>= 1) {
        if (t < sdt) red[t] += red[t + sdt];
        __syncthreads();
    }
    float var = red[0] * (1.0f / DD);
    Y[row * DD + t] = d * rsqrtf(var + 1e-5f) * s[t] + bb[t];
}

// ---------------- 10) logits = H @ w2 + b2 (one warp per token) ----------------
__global__ void k_logits(const float* __restrict__ H, const float* __restrict__ w2,
                         const float* __restrict__ b2) {
    int warp = threadIdx.x >> 5, lane = threadIdx.x & 31;
    int n = blockIdx.x * 8 + warp;
    float ssum = 0.f;
    for (int i = lane; i < DD; i += 32) ssum = fmaf(H[n * DD + i], w2[i], ssum);
#pragma unroll
    for (int off = 16; off; off >>= 1) ssum += __shfl_down_sync(0xffffffff, ssum, off);
    if (lane == 0) g_logits[n] = ssum + b2[0];
}

// ---------------- 11) dec: paint 4x4 dec_w per token -> patch_logits ----------------
__global__ void k_dec(const float* __restrict__ dec_w, const float* __restrict__ dec_b,
                      float* __restrict__ out_plog) {
    int bk = blockIdx.x;            // 0..255
    int b = bk >> 4, k = bk & 15;
    int t = threadIdx.x;            // pixel
    int y = t >> 4, x = t & 15;
    int i = y >> 2, a = y & 3, j = x >> 2, c = x & 3;
    float v = g_logits[b * SEQ + k * 16 + i * 4 + j] * __ldg(&dec_w[a * 4 + c]) + dec_b[0];
    out_plog[bk * 256 + t] = v;
}

// ---------------- 12) final assembly ----------------
__global__ void k_final(const float* __restrict__ plog, float* __restrict__ out_final) {
    int idx = blockIdx.x * blockDim.x + threadIdx.x;   // B*1024*1024
    int b = idx >> 20;
    int y = (idx >> 10) & 1023;
    int x = idx & 1023;
    int p = (y >> 4) * NW_ + (x >> 4);
    int k = g_map[b * NPATCH + p];
    float v = 0.f;
    if (k >= 0) v = plog[(b * 16 + k) * 256 + (y & 15) * 16 + (x & 15)];
    out_final[idx] = v;
}

// ---------------- launch ----------------
extern "C" void kernel_launch(void* const* d_in, const int* in_sizes, int n_in,
                              void* d_out, int out_size) {
    const float* image     = (const float*)d_in[0];
    const float* labels    = (const float*)d_in[1];
    const float* pe_w      = (const float*)d_in[2];
    const float* pe_b      = (const float*)d_in[3];
    const float* pos_embed = (const float*)d_in[4];
    const float* in_proj_w = (const float*)d_in[5];
    const float* in_proj_b = (const float*)d_in[6];
    const float* out_w     = (const float*)d_in[7];
    const float* out_b     = (const float*)d_in[8];
    const float* ln1_s     = (const float*)d_in[9];
    const float* ln1_b     = (const float*)d_in[10];
    const float* ff1_w     = (const float*)d_in[11];
    const float* ff1_b     = (const float*)d_in[12];
    const float* ff2_w     = (const float*)d_in[13];
    const float* ff2_b     = (const float*)d_in[14];
    const float* ln2_s     = (const float*)d_in[15];
    const float* ln2_b     = (const float*)d_in[16];
    const float* head_ln_s = (const float*)d_in[17];
    const float* head_ln_b = (const float*)d_in[18];
    const float* head_w1   = (const float*)d_in[19];
    const float* head_b1   = (const float*)d_in[20];
    const float* head_w2   = (const float*)d_in[21];
    const float* head_b2   = (const float*)d_in[22];
    const float* dec_w     = (const float*)d_in[23];
    const float* dec_b     = (const float*)d_in[24];

    float* out = (float*)d_out;
    float* out_coarse = out + OFF_COARSE;
    float* out_patch  = out + OFF_PATCH;
    float* out_plab   = out + OFF_PLAB;
    float* out_coord  = out + OFF_COORD;
    float* out_plog   = out + OFF_PLOG;
    float* out_final  = out + OFF_FINAL;

    // device scratch pointers
    float *pX, *pQKV, *pT1, *pT2;
    cudaGetSymbolAddress((void**)&pX,   g_X);
    cudaGetSymbolAddress((void**)&pQKV, g_QKV);
    cudaGetSymbolAddress((void**)&pT1,  g_T1);
    cudaGetSymbolAddress((void**)&pT2,  g_T2);

    // global branch
    k_coarse <<< (BB * 256 * 256) / 256, 256 >>> (labels, out_coarse);
    k_scores <<< (BB * NPATCH) / 256, 256 >>> (out_coarse);
    k_mapinit<<< (BB * NPATCH + 255) / 256, 256 >>> ();
    k_topk   <<< BB, 256 >>> ();
    k_gather <<< BB * KK, 256 >>> (image, labels, out_patch, out_plab, out_coord);

    // local branch: tokens
    k_embed  <<< NTOK, 256 >>> (out_patch, pe_w, pe_b, pos_embed);

    for (int l = 0; l < NL; l++) {
        // qkv
        k_sgemm <<< dim3(3 * DD / 64, NTOK / 64), 256 >>> (
            pX, in_proj_w + l * 3 * DD * DD, in_proj_b + l * 3 * DD, pQKV,
            NTOK, 3 * DD, DD, 0);
        // attention
        k_attn <<< BB * NH, 256 >>> (pQKV, pT2);
        // out proj -> T1 (used as [NTOK,DD])
        k_sgemm <<< dim3(DD / 64, NTOK / 64), 256 >>> (
            pT2, out_w + l * DD * DD, out_b + l * DD, pT1,
            NTOK, DD, DD, 0);
        // X = LN(X + proj)
        k_ln <<< NTOK, 256 >>> (pX, pT1, ln1_s + l * DD, ln1_b + l * DD, pX, 1);
        // ff1 + gelu
        k_sgemm <<< dim3(DFF / 64, NTOK / 64), 256 >>> (
            pX, ff1_w + l * DFF * DD, ff1_b + l * DFF, pT1,
            NTOK, DFF, DD, 1);
        // ff2
        k_sgemm <<< dim3(DD / 64, NTOK / 64), 256 >>> (
            pT1, ff2_w + l * DD * DFF, ff2_b + l * DD, pT2,
            NTOK, DD, DFF, 0);
        // X = LN(X + ff)
        k_ln <<< NTOK, 256 >>> (pX, pT2, ln2_s + l * DD, ln2_b + l * DD, pX, 1);
    }

    // head
    k_ln <<< NTOK, 256 >>> (pX, nullptr, head_ln_s, head_ln_b, pT2, 0);
    k_sgemm <<< dim3(DD / 64, NTOK / 64), 256 >>> (
        pT2, head_w1, head_b1, pT1, NTOK, DD, DD, 1);
    k_logits <<< NTOK / 8, 256 >>> (pT1, head_w2, head_b2);

    // decode + assemble
    k_dec   <<< BB * KK, 256 >>> (dec_w, dec_b, out_plog);
    k_final <<< (BB * HH * WW) / 256, 256 >>> (out_plog, out_final);
}

// round 9
// speedup vs baseline: 1.0014x; 1.0014x over previous
#include <cuda_runtime.h>
#include <cuda_bf16.h>
#include <math.h>

// ---------------- constants ----------------
#define BB 16          // batch
#define HH 1024
#define WW 1024
#define PS 16
#define IPS 4
#define CS 4
#define KK 16          // top-k patches
#define DD 256         // model dim
#define NH 4
#define DH 64
#define DFF 1024
#define NL 2
#define NW_ 64         // patches per row = 1024/16
#define NPATCH 4096    // 64*64
#define SEQ 256        // tokens per batch = K*16
#define NTOK 4096      // B*SEQ

// output layout (f32 element offsets, tuple concatenated flat)
#define LEN_COARSE (BB*256*256)              // 1048576
#define OFF_COARSE 0
#define OFF_PATCH  (OFF_COARSE + LEN_COARSE)
#define LEN_PATCH  (BB*KK*PS*PS)             // 65536
#define OFF_PLAB   (OFF_PATCH + LEN_PATCH)
#define OFF_COORD  (OFF_PLAB + LEN_PATCH)
#define LEN_COORD  (BB*KK*2)                 // 512
#define OFF_PLOG   (OFF_COORD + LEN_COORD)
#define OFF_FINAL  (OFF_PLOG + LEN_PATCH)

// ---------------- scratch (static device globals; no allocation) ----------------
__device__ float g_scores[BB * NPATCH];
__device__ int   g_idx[BB * KK];
__device__ int   g_map[BB * NPATCH];
__device__ float g_X   [NTOK * DD];      // tokens
__device__ float g_QKV [NTOK * 3 * DD];  // qkv
__device__ float g_T1  [NTOK * DFF];     // ff hidden / proj / head gelu
__device__ float g_T2  [NTOK * DD];      // attn concat / ff out / head ln
__device__ float g_logits[NTOK];

__device__ __forceinline__ float gelu_exact(float v) {
    return 0.5f * v * (1.0f + erff(v * 0.70710678118654752f));
}

// ---------------- 1) coarse = avgpool4x4(labels) -> out ----------------
__global__ void k_coarse(const float* __restrict__ labels, float* __restrict__ out_coarse) {
    int idx = blockIdx.x * blockDim.x + threadIdx.x;   // B*256*256
    int b  = idx >> 16;
    int yc = (idx >> 8) & 255;
    int xc = idx & 255;
    const float* lp = labels + b * (HH * WW) + (yc * 4) * WW + xc * 4;
    float s = 0.f;
#pragma unroll
    for (int dy = 0; dy < 4; dy++)
#pragma unroll
        for (int dx = 0; dx < 4; dx++) s += lp[dy * WW + dx];
    out_coarse[idx] = s * 0.0625f;
}

// ---------------- 2) per-patch score = avgpool4x4(coarse) ----------------
__global__ void k_scores(const float* __restrict__ coarse) {
    int idx = blockIdx.x * blockDim.x + threadIdx.x;   // B*4096
    int b = idx >> 12;
    int p = idx & 4095;
    int hi = p >> 6, wi = p & 63;
    const float* cp = coarse + b * 65536 + (hi * 4) * 256 + wi * 4;
    float s = 0.f;
#pragma unroll
    for (int dy = 0; dy < 4; dy++)
#pragma unroll
        for (int dx = 0; dx < 4; dx++) s += cp[dy * 256 + dx];
    g_scores[idx] = s * 0.0625f;
}

// ---------------- 3) map init ----------------
__global__ void k_mapinit() {
    int idx = blockIdx.x * blockDim.x + threadIdx.x;
    if (idx < BB * NPATCH) g_map[idx] = -1;
}

// ---------------- 4) top-K per batch (descending, lower index on ties) ----------------
__global__ void k_topk() {
    int b = blockIdx.x;
    __shared__ float sv[NPATCH];
    __shared__ float rv[256];
    __shared__ int   ri[256];
    for (int i = threadIdx.x; i < NPATCH; i += 256) sv[i] = g_scores[b * NPATCH + i];
    __syncthreads();
    for (int it = 0; it < KK; it++) {
        float best = -3.0e38f; int bi = NPATCH;
        for (int i = threadIdx.x; i < NPATCH; i += 256) {
            float v = sv[i];
            if (v > best) { best = v; bi = i; }   // ascending scan keeps lowest idx on ties
        }
        rv[threadIdx.x] = best; ri[threadIdx.x] = bi;
        __syncthreads();
        for (int s = 128; s > 0; s >>= 1) {
            if (threadIdx.x < s) {
                float v2 = rv[threadIdx.x + s]; int i2 = ri[threadIdx.x + s];
                if (v2 > rv[threadIdx.x] || (v2 == rv[threadIdx.x] && i2 < ri[threadIdx.x])) {
                    rv[threadIdx.x] = v2; ri[threadIdx.x] = i2;
                }
            }
            __syncthreads();
        }
        if (threadIdx.x == 0) { g_idx[b * KK + it] = ri[0]; sv[ri[0]] = -3.0e38f; }
        __syncthreads();
    }
}

// ---------------- 5) gather patches / labels / coords / map ----------------
__global__ void k_gather(const float* __restrict__ image, const float* __restrict__ labels,
                         float* __restrict__ out_p, float* __restrict__ out_l,
                         float* __restrict__ out_c) {
    int bk = blockIdx.x;            // 0..255
    int b = bk >> 4, k = bk & 15;
    int pidx = g_idx[bk];
    int hi = pidx >> 6, wi = pidx & 63;
    int t = threadIdx.x;
    int py = t >> 4, px = t & 15;
    int base = b * (HH * WW) + (hi * 16 + py) * WW + wi * 16 + px;
    out_p[bk * 256 + t] = image[base];
    out_l[bk * 256 + t] = labels[base];
    if (t == 0) {
        out_c[bk * 2 + 0] = (float)(hi * 16);
        out_c[bk * 2 + 1] = (float)(wi * 16);
        g_map[b * NPATCH + pidx] = k;
    }
}

// ---------------- 6) patch embed: tokens = conv4x4(pe_w) + pe_b + pos ----------------
__global__ void k_embed(const float* __restrict__ patches, const float* __restrict__ pe_w,
                        const float* __restrict__ pe_b, const float* __restrict__ pos) {
    int n = blockIdx.x;             // token 0..4095
    int d = threadIdx.x;            // 0..255
    int r = n & 255;
    int b = n >> 8;
    int k = r >> 4, q = r & 15;
    int i = q >> 2, j = q & 3;
    __shared__ float sub[16];
    if (d < 16) {
        int a = d >> 2, bb = d & 3;
        sub[d] = patches[(b * 16 + k) * 256 + (i * 4 + a) * 16 + (j * 4 + bb)];
    }
    __syncthreads();
    float s = pe_b[d] + pos[q * DD + d];
#pragma unroll
    for (int p = 0; p < 16; p++) s += __ldg(&pe_w[d * 16 + p]) * sub[p];
    g_X[n * DD + d] = s;
}

// ---------------- 7) SGEMM: C[M,N] = act(A[M,K] * W[N,K]^T + bias) ----------------
// 64x64 tile, BK=16, 256 threads, 4x4 per thread
__global__ __launch_bounds__(256) void k_sgemm(const float* __restrict__ A,
                                               const float* __restrict__ W,
                                               const float* __restrict__ bias,
                                               float* __restrict__ C,
                                               int M, int N, int Kd, int act) {
    __shared__ float As[16][68];
    __shared__ float Bs[16][68];
    int n0 = blockIdx.x * 64;
    int m0 = blockIdx.y * 64;
    int t = threadIdx.x;
    int tx = t & 15, ty = t >> 4;
    int lrow = t >> 2;
    int lk = (t & 3) * 4;
    float acc[4][4];
#pragma unroll
    for (int i = 0; i < 4; i++)
#pragma unroll
        for (int j = 0; j < 4; j++) acc[i][j] = 0.f;

    const float* Ap = A + (m0 + lrow) * Kd + lk;
    const float* Wp = W + (n0 + lrow) * Kd + lk;

    for (int k0 = 0; k0 < Kd; k0 += 16) {
        float4 a4 = *(const float4*)(Ap + k0);
        float4 b4 = *(const float4*)(Wp + k0);
        __syncthreads();
        As[lk + 0][lrow] = a4.x; As[lk + 1][lrow] = a4.y;
        As[lk + 2][lrow] = a4.z; As[lk + 3][lrow] = a4.w;
        Bs[lk + 0][lrow] = b4.x; Bs[lk + 1][lrow] = b4.y;
        Bs[lk + 2][lrow] = b4.z; Bs[lk + 3][lrow] = b4.w;
        __syncthreads();
#pragma unroll
        for (int kk = 0; kk < 16; kk++) {
            float4 av = *(const float4*)&As[kk][ty * 4];
            float4 bv = *(const float4*)&Bs[kk][tx * 4];
            float ar[4] = {av.x, av.y, av.z, av.w};
            float br[4] = {bv.x, bv.y, bv.z, bv.w};
#pragma unroll
            for (int i = 0; i < 4; i++)
#pragma unroll
                for (int j = 0; j < 4; j++) acc[i][j] = fmaf(ar[i], br[j], acc[i][j]);
        }
    }
#pragma unroll
    for (int i = 0; i < 4; i++) {
        int m = m0 + ty * 4 + i;
#pragma unroll
        for (int j = 0; j < 4; j++) {
            int n = n0 + tx * 4 + j;
            float v = acc[i][j] + bias[n];
            if (act) v = gelu_exact(v);
            C[m * N + n] = v;
        }
    }
}

// ---------------- 8) attention: one block per (b,h), flash-style ----------------
__global__ __launch_bounds__(256, 1) void k_attn(const float* __restrict__ QKV,
                                                 float* __restrict__ O) {
    int b = blockIdx.x >> 2;
    int h = blockIdx.x & 3;
    __shared__ float Ks[64 * 64];
    __shared__ float Vs[64 * 64];
    int q = threadIdx.x;            // query token 0..255

    float qreg[64];
    {
        const float4* qp = (const float4*)(QKV + ((b * SEQ + q) * 3 * DD) + h * DH);
#pragma unroll
        for (int d4 = 0; d4 < 16; d4++) {
            float4 v = qp[d4];
            qreg[d4 * 4 + 0] = v.x * 0.125f;
            qreg[d4 * 4 + 1] = v.y * 0.125f;
            qreg[d4 * 4 + 2] = v.z * 0.125f;
            qreg[d4 * 4 + 3] = v.w * 0.125f;
        }
    }
    float o[64];
#pragma unroll
    for (int d = 0; d < 64; d++) o[d] = 0.f;
    float m = -3.0e38f, l = 0.f;

    for (int tile = 0; tile < 4; tile++) {
        __syncthreads();
        for (int i = threadIdx.x; i < 4096; i += 256) {
            int tok = i >> 6, d = i & 63;
            int gbase = (b * SEQ + tile * 64 + tok) * 3 * DD + h * DH + d;
            Ks[i] = QKV[gbase + DD];
            Vs[i] = QKV[gbase + 2 * DD];
        }
        __syncthreads();
#pragma unroll 2
        for (int j = 0; j < 64; j++) {
            const float4* kp = (const float4*)&Ks[j * 64];
            float s = 0.f;
#pragma unroll
            for (int d4 = 0; d4 < 16; d4++) {
                float4 kv = kp[d4];
                s = fmaf(qreg[d4 * 4 + 0], kv.x, s);
                s = fmaf(qreg[d4 * 4 + 1], kv.y, s);
                s = fmaf(qreg[d4 * 4 + 2], kv.z, s);
                s = fmaf(qreg[d4 * 4 + 3], kv.w, s);
            }
            float mn = fmaxf(m, s);
            float c = expf(m - mn);
            float p = expf(s - mn);
            l = l * c + p;
            const float4* vp = (const float4*)&Vs[j * 64];
#pragma unroll
            for (int d4 = 0; d4 < 16; d4++) {
                float4 vv = vp[d4];
                o[d4 * 4 + 0] = fmaf(o[d4 * 4 + 0], c, p * vv.x);
                o[d4 * 4 + 1] = fmaf(o[d4 * 4 + 1], c, p * vv.y);
                o[d4 * 4 + 2] = fmaf(o[d4 * 4 + 2], c, p * vv.z);
                o[d4 * 4 + 3] = fmaf(o[d4 * 4 + 3], c, p * vv.w);
            }
            m = mn;
        }
    }
    float inv = 1.f / l;
    float4* op = (float4*)(O + (b * SEQ + q) * DD + h * DH);
#pragma unroll
    for (int d4 = 0; d4 < 16; d4++) {
        float4 v;
        v.x = o[d4 * 4 + 0] * inv; v.y = o[d4 * 4 + 1] * inv;
        v.z = o[d4 * 4 + 2] * inv; v.w = o[d4 * 4 + 3] * inv;
        op[d4] = v;
    }
}

// ---------------- 9) layernorm (optional residual), row = one block ----------------
__global__ void k_ln(const float* __restrict__ X, const float* __restrict__ R,
                     const float* __restrict__ s, const float* __restrict__ bb,
                     float* __restrict__ Y, int hasRes) {
    int row = blockIdx.x;
    int t = threadIdx.x;
    __shared__ float red[256];
    float x = X[row * DD + t];
    if (hasRes) x += R[row * DD + t];
    red[t] = x;
    __syncthreads();
    for (int sdt = 128; sdt > 0; sdt >>= 1) {
        if (t < sdt) red[t] += red[t + sdt];
        __syncthreads();
    }
    float mean = red[0] * (1.0f / DD);
    __syncthreads();
    float d = x - mean;
    red[t] = d * d;
    __syncthreads();
    for (int sdt = 128; sdt > 0; sdt >>= 1) {
        if (t < sdt) red[t] += red[t + sdt];
        __syncthreads();
    }
    float var = red[0] * (1.0f / DD);
    Y[row * DD + t] = d * rsqrtf(var + 1e-5f) * s[t] + bb[t];
}

// ---------------- 10) logits = H @ w2 + b2 (one warp per token) ----------------
__global__ void k_logits(const float* __restrict__ H, const float* __restrict__ w2,
                         const float* __restrict__ b2) {
    int warp = threadIdx.x >> 5, lane = threadIdx.x & 31;
    int n = blockIdx.x * 8 + warp;
    float ssum = 0.f;
    for (int i = lane; i < DD; i += 32) ssum = fmaf(H[n * DD + i], w2[i], ssum);
#pragma unroll
    for (int off = 16; off; off >>= 1) ssum += __shfl_down_sync(0xffffffff, ssum, off);
    if (lane == 0) g_logits[n] = ssum + b2[0];
}

// ---------------- 11) dec: paint 4x4 dec_w per token -> patch_logits ----------------
__global__ void k_dec(const float* __restrict__ dec_w, const float* __restrict__ dec_b,
                      float* __restrict__ out_plog) {
    int bk = blockIdx.x;            // 0..255
    int b = bk >> 4, k = bk & 15;
    int t = threadIdx.x;            // pixel
    int y = t >> 4, x = t & 15;
    int i = y >> 2, a = y & 3, j = x >> 2, c = x & 3;
    float v = g_logits[b * SEQ + k * 16 + i * 4 + j] * __ldg(&dec_w[a * 4 + c]) + dec_b[0];
    out_plog[bk * 256 + t] = v;
}

// ---------------- 12) final assembly ----------------
__global__ void k_final(const float* __restrict__ plog, float* __restrict__ out_final) {
    int idx = blockIdx.x * blockDim.x + threadIdx.x;   // B*1024*1024
    int b = idx >> 20;
    int y = (idx >> 10) & 1023;
    int x = idx & 1023;
    int p = (y >> 4) * NW_ + (x >> 4);
    int k = g_map[b * NPATCH + p];
    float v = 0.f;
    if (k >= 0) v = plog[(b * 16 + k) * 256 + (y & 15) * 16 + (x & 15)];
    out_final[idx] = v;
}

// ---------------- launch ----------------
extern "C" void kernel_launch(void* const* d_in, const int* in_sizes, int n_in,
                              void* d_out, int out_size) {
    const float* image     = (const float*)d_in[0];
    const float* labels    = (const float*)d_in[1];
    const float* pe_w      = (const float*)d_in[2];
    const float* pe_b      = (const float*)d_in[3];
    const float* pos_embed = (const float*)d_in[4];
    const float* in_proj_w = (const float*)d_in[5];
    const float* in_proj_b = (const float*)d_in[6];
    const float* out_w     = (const float*)d_in[7];
    const float* out_b     = (const float*)d_in[8];
    const float* ln1_s     = (const float*)d_in[9];
    const float* ln1_b     = (const float*)d_in[10];
    const float* ff1_w     = (const float*)d_in[11];
    const float* ff1_b     = (const float*)d_in[12];
    const float* ff2_w     = (const float*)d_in[13];
    const float* ff2_b     = (const float*)d_in[14];
    const float* ln2_s     = (const float*)d_in[15];
    const float* ln2_b     = (const float*)d_in[16];
    const float* head_ln_s = (const float*)d_in[17];
    const float* head_ln_b = (const float*)d_in[18];
    const float* head_w1   = (const float*)d_in[19];
    const float* head_b1   = (const float*)d_in[20];
    const float* head_w2   = (const float*)d_in[21];
    const float* head_b2   = (const float*)d_in[22];
    const float* dec_w     = (const float*)d_in[23];
    const float* dec_b     = (const float*)d_in[24];

    float* out = (float*)d_out;
    float* out_coarse = out + OFF_COARSE;
    float* out_patch  = out + OFF_PATCH;
    float* out_plab   = out + OFF_PLAB;
    float* out_coord  = out + OFF_COORD;
    float* out_plog   = out + OFF_PLOG;
    float* out_final  = out + OFF_FINAL;

    // device scratch pointers
    float *pX, *pQKV, *pT1, *pT2;
    cudaGetSymbolAddress((void**)&pX,   g_X);
    cudaGetSymbolAddress((void**)&pQKV, g_QKV);
    cudaGetSymbolAddress((void**)&pT1,  g_T1);
    cudaGetSymbolAddress((void**)&pT2,  g_T2);

    // global branch
    k_coarse <<< (BB * 256 * 256) / 256, 256 >>> (labels, out_coarse);
    k_scores <<< (BB * NPATCH) / 256, 256 >>> (out_coarse);
    k_mapinit<<< (BB * NPATCH + 255) / 256, 256 >>> ();
    k_topk   <<< BB, 256 >>> ();
    k_gather <<< BB * KK, 256 >>> (image, labels, out_patch, out_plab, out_coord);

    // local branch: tokens
    k_embed  <<< NTOK, 256 >>> (out_patch, pe_w, pe_b, pos_embed);

    for (int l = 0; l < NL; l++) {
        // qkv
        k_sgemm <<< dim3(3 * DD / 64, NTOK / 64), 256 >>> (
            pX, in_proj_w + l * 3 * DD * DD, in_proj_b + l * 3 * DD, pQKV,
            NTOK, 3 * DD, DD, 0);
        // attention
        k_attn <<< BB * NH, 256 >>> (pQKV, pT2);
        // out proj -> T1 (used as [NTOK,DD])
        k_sgemm <<< dim3(DD / 64, NTOK / 64), 256 >>> (
            pT2, out_w + l * DD * DD, out_b + l * DD, pT1,
            NTOK, DD, DD, 0);
        // X = LN(X + proj)
        k_ln <<< NTOK, 256 >>> (pX, pT1, ln1_s + l * DD, ln1_b + l * DD, pX, 1);
        // ff1 + gelu
        k_sgemm <<< dim3(DFF / 64, NTOK / 64), 256 >>> (
            pX, ff1_w + l * DFF * DD, ff1_b + l * DFF, pT1,
            NTOK, DFF, DD, 1);
        // ff2
        k_sgemm <<< dim3(DD / 64, NTOK / 64), 256 >>> (
            pT1, ff2_w + l * DD * DFF, ff2_b + l * DD, pT2,
            NTOK, DD, DFF, 0);
        // X = LN(X + ff)
        k_ln <<< NTOK, 256 >>> (pX, pT2, ln2_s + l * DD, ln2_b + l * DD, pX, 1);
    }

    // head
    k_ln <<< NTOK, 256 >>> (pX, nullptr, head_ln_s, head_ln_b, pT2, 0);
    k_sgemm <<< dim3(DD / 64, NTOK / 64), 256 >>> (
        pT2, head_w1, head_b1, pT1, NTOK, DD, DD, 1);
    k_logits <<< NTOK / 8, 256 >>> (pT1, head_w2, head_b2);

    // decode + assemble
    k_dec   <<< BB * KK, 256 >>> (dec_w, dec_b, out_plog);
    k_final <<< (BB * HH * WW) / 256, 256 >>> (out_plog, out_final);
}

// round 10
// speedup vs baseline: 1.0020x; 1.0006x over previous
#include <cuda_runtime.h>
#include <cuda_bf16.h>
#include <math.h>

// ---------------- constants ----------------
#define BB 16          // batch
#define HH 1024
#define WW 1024
#define PS 16
#define IPS 4
#define CS 4
#define KK 16          // top-k patches
#define DD 256         // model dim
#define NH 4
#define DH 64
#define DFF 1024
#define NL 2
#define NW_ 64         // patches per row = 1024/16
#define NPATCH 4096    // 64*64
#define SEQ 256        // tokens per batch = K*16
#define NTOK 4096      // B*SEQ

// output layout (f32 element offsets, tuple concatenated flat)
#define LEN_COARSE (BB*256*256)              // 1048576
#define OFF_COARSE 0
#define OFF_PATCH  (OFF_COARSE + LEN_COARSE)
#define LEN_PATCH  (BB*KK*PS*PS)             // 65536
#define OFF_PLAB   (OFF_PATCH + LEN_PATCH)
#define OFF_COORD  (OFF_PLAB + LEN_PATCH)
#define LEN_COORD  (BB*KK*2)                 // 512
#define OFF_PLOG   (OFF_COORD + LEN_COORD)
#define OFF_FINAL  (OFF_PLOG + LEN_PATCH)

// ---------------- scratch (static device globals; no allocation) ----------------
__device__ float g_scores[BB * NPATCH];
__device__ int   g_idx[BB * KK];
__device__ int   g_map[BB * NPATCH];
__device__ float g_X   [NTOK * DD];      // tokens
__device__ float g_QKV [NTOK * 3 * DD];  // qkv
__device__ float g_T1  [NTOK * DFF];     // ff hidden / proj / head gelu
__device__ float g_T2  [NTOK * DD];      // attn concat / ff out / head ln
__device__ float g_logits[NTOK];

__device__ __forceinline__ float gelu_exact(float v) {
    return 0.5f * v * (1.0f + erff(v * 0.70710678118654752f));
}

// ---------------- 1) coarse = avgpool4x4(labels) -> out ----------------
__global__ void k_coarse(const float* __restrict__ labels, float* __restrict__ out_coarse) {
    int idx = blockIdx.x * blockDim.x + threadIdx.x;   // B*256*256
    int b  = idx >> 16;
    int yc = (idx >> 8) & 255;
    int xc = idx & 255;
    const float* lp = labels + b * (HH * WW) + (yc * 4) * WW + xc * 4;
    float s = 0.f;
#pragma unroll
    for (int dy = 0; dy < 4; dy++)
#pragma unroll
        for (int dx = 0; dx < 4; dx++) s += lp[dy * WW + dx];
    out_coarse[idx] = s * 0.0625f;
}

// ---------------- 2) per-patch score = avgpool4x4(coarse) ----------------
__global__ void k_scores(const float* __restrict__ coarse) {
    int idx = blockIdx.x * blockDim.x + threadIdx.x;   // B*4096
    int b = idx >> 12;
    int p = idx & 4095;
    int hi = p >> 6, wi = p & 63;
    const float* cp = coarse + b * 65536 + (hi * 4) * 256 + wi * 4;
    float s = 0.f;
#pragma unroll
    for (int dy = 0; dy < 4; dy++)
#pragma unroll
        for (int dx = 0; dx < 4; dx++) s += cp[dy * 256 + dx];
    g_scores[idx] = s * 0.0625f;
}

// ---------------- 3) map init ----------------
__global__ void k_mapinit() {
    int idx = blockIdx.x * blockDim.x + threadIdx.x;
    if (idx < BB * NPATCH) g_map[idx] = -1;
}

// ---------------- 4) top-K per batch (descending, lower index on ties) ----------------
__global__ void k_topk() {
    int b = blockIdx.x;
    __shared__ float sv[NPATCH];
    __shared__ float rv[256];
    __shared__ int   ri[256];
    for (int i = threadIdx.x; i < NPATCH; i += 256) sv[i] = g_scores[b * NPATCH + i];
    __syncthreads();
    for (int it = 0; it < KK; it++) {
        float best = -3.0e38f; int bi = NPATCH;
        for (int i = threadIdx.x; i < NPATCH; i += 256) {
            float v = sv[i];
            if (v > best) { best = v; bi = i; }   // ascending scan keeps lowest idx on ties
        }
        rv[threadIdx.x] = best; ri[threadIdx.x] = bi;
        __syncthreads();
        for (int s = 128; s > 0; s >>= 1) {
            if (threadIdx.x < s) {
                float v2 = rv[threadIdx.x + s]; int i2 = ri[threadIdx.x + s];
                if (v2 > rv[threadIdx.x] || (v2 == rv[threadIdx.x] && i2 < ri[threadIdx.x])) {
                    rv[threadIdx.x] = v2; ri[threadIdx.x] = i2;
                }
            }
            __syncthreads();
        }
        if (threadIdx.x == 0) { g_idx[b * KK + it] = ri[0]; sv[ri[0]] = -3.0e38f; }
        __syncthreads();
    }
}

// ---------------- 5) gather patches / labels / coords / map ----------------
__global__ void k_gather(const float* __restrict__ image, const float* __restrict__ labels,
                         float* __restrict__ out_p, float* __restrict__ out_l,
                         float* __restrict__ out_c) {
    int bk = blockIdx.x;            // 0..255
    int b = bk >> 4, k = bk & 15;
    int pidx = g_idx[bk];
    int hi = pidx >> 6, wi = pidx & 63;
    int t = threadIdx.x;
    int py = t >> 4, px = t & 15;
    int base = b * (HH * WW) + (hi * 16 + py) * WW + wi * 16 + px;
    out_p[bk * 256 + t] = image[base];
    out_l[bk * 256 + t] = labels[base];
    if (t == 0) {
        out_c[bk * 2 + 0] = (float)(hi * 16);
        out_c[bk * 2 + 1] = (float)(wi * 16);
        g_map[b * NPATCH + pidx] = k;
    }
}

// ---------------- 6) patch embed: tokens = conv4x4(pe_w) + pe_b + pos ----------------
__global__ void k_embed(const float* __restrict__ patches, const float* __restrict__ pe_w,
                        const float* __restrict__ pe_b, const float* __restrict__ pos) {
    int n = blockIdx.x;             // token 0..4095
    int d = threadIdx.x;            // 0..255
    int r = n & 255;
    int b = n >> 8;
    int k = r >> 4, q = r & 15;
    int i = q >> 2, j = q & 3;
    __shared__ float sub[16];
    if (d < 16) {
        int a = d >> 2, bb = d & 3;
        sub[d] = patches[(b * 16 + k) * 256 + (i * 4 + a) * 16 + (j * 4 + bb)];
    }
    __syncthreads();
    float s = pe_b[d] + pos[q * DD + d];
#pragma unroll
    for (int p = 0; p < 16; p++) s += __ldg(&pe_w[d * 16 + p]) * sub[p];
    g_X[n * DD + d] = s;
}

// ---------------- 7) SGEMM: C[M,N] = act(A[M,K] * W[N,K]^T + bias) ----------------
// 64x64 tile, BK=16, 256 threads, 4x4 per thread
__global__ __launch_bounds__(256) void k_sgemm(const float* __restrict__ A,
                                               const float* __restrict__ W,
                                               const float* __restrict__ bias,
                                               float* __restrict__ C,
                                               int M, int N, int Kd, int act) {
    __shared__ float As[16][68];
    __shared__ float Bs[16][68];
    int n0 = blockIdx.x * 64;
    int m0 = blockIdx.y * 64;
    int t = threadIdx.x;
    int tx = t & 15, ty = t >> 4;
    int lrow = t >> 2;
    int lk = (t & 3) * 4;
    float acc[4][4];
#pragma unroll
    for (int i = 0; i < 4; i++)
#pragma unroll
        for (int j = 0; j < 4; j++) acc[i][j] = 0.f;

    const float* Ap = A + (m0 + lrow) * Kd + lk;
    const float* Wp = W + (n0 + lrow) * Kd + lk;

    for (int k0 = 0; k0 < Kd; k0 += 16) {
        float4 a4 = *(const float4*)(Ap + k0);
        float4 b4 = *(const float4*)(Wp + k0);
        __syncthreads();
        As[lk + 0][lrow] = a4.x; As[lk + 1][lrow] = a4.y;
        As[lk + 2][lrow] = a4.z; As[lk + 3][lrow] = a4.w;
        Bs[lk + 0][lrow] = b4.x; Bs[lk + 1][lrow] = b4.y;
        Bs[lk + 2][lrow] = b4.z; Bs[lk + 3][lrow] = b4.w;
        __syncthreads();
#pragma unroll
        for (int kk = 0; kk < 16; kk++) {
            float4 av = *(const float4*)&As[kk][ty * 4];
            float4 bv = *(const float4*)&Bs[kk][tx * 4];
            float ar[4] = {av.x, av.y, av.z, av.w};
            float br[4] = {bv.x, bv.y, bv.z, bv.w};
#pragma unroll
            for (int i = 0; i < 4; i++)
#pragma unroll
                for (int j = 0; j < 4; j++) acc[i][j] = fmaf(ar[i], br[j], acc[i][j]);
        }
    }
#pragma unroll
    for (int i = 0; i < 4; i++) {
        int m = m0 + ty * 4 + i;
#pragma unroll
        for (int j = 0; j < 4; j++) {
            int n = n0 + tx * 4 + j;
            float v = acc[i][j] + bias[n];
            if (act) v = gelu_exact(v);
            C[m * N + n] = v;
        }
    }
}

// ---------------- 8) attention: one block per (b,h), flash-style ----------------
__global__ __launch_bounds__(256, 1) void k_attn(const float* __restrict__ QKV,
                                                 float* __restrict__ O) {
    int b = blockIdx.x >> 2;
    int h = blockIdx.x & 3;
    __shared__ float Ks[64 * 64];
    __shared__ float Vs[64 * 64];
    int q = threadIdx.x;            // query token 0..255

    float qreg[64];
    {
        const float4* qp = (const float4*)(QKV + ((b * SEQ + q) * 3 * DD) + h * DH);
#pragma unroll
        for (int d4 = 0; d4 < 16; d4++) {
            float4 v = qp[d4];
            qreg[d4 * 4 + 0] = v.x * 0.125f;
            qreg[d4 * 4 + 1] = v.y * 0.125f;
            qreg[d4 * 4 + 2] = v.z * 0.125f;
            qreg[d4 * 4 + 3] = v.w * 0.125f;
        }
    }
    float o[64];
#pragma unroll
    for (int d = 0; d < 64; d++) o[d] = 0.f;
    float m = -3.0e38f, l = 0.f;

    for (int tile = 0; tile < 4; tile++) {
        __syncthreads();
        for (int i = threadIdx.x; i < 4096; i += 256) {
            int tok = i >> 6, d = i & 63;
            int gbase = (b * SEQ + tile * 64 + tok) * 3 * DD + h * DH + d;
            Ks[i] = QKV[gbase + DD];
            Vs[i] = QKV[gbase + 2 * DD];
        }
        __syncthreads();
#pragma unroll 2
        for (int j = 0; j < 64; j++) {
            const float4* kp = (const float4*)&Ks[j * 64];
            float s = 0.f;
#pragma unroll
            for (int d4 = 0; d4 < 16; d4++) {
                float4 kv = kp[d4];
                s = fmaf(qreg[d4 * 4 + 0], kv.x, s);
                s = fmaf(qreg[d4 * 4 + 1], kv.y, s);
                s = fmaf(qreg[d4 * 4 + 2], kv.z, s);
                s = fmaf(qreg[d4 * 4 + 3], kv.w, s);
            }
            float mn = fmaxf(m, s);
            float c = expf(m - mn);
            float p = expf(s - mn);
            l = l * c + p;
            const float4* vp = (const float4*)&Vs[j * 64];
#pragma unroll
            for (int d4 = 0; d4 < 16; d4++) {
                float4 vv = vp[d4];
                o[d4 * 4 + 0] = fmaf(o[d4 * 4 + 0], c, p * vv.x);
                o[d4 * 4 + 1] = fmaf(o[d4 * 4 + 1], c, p * vv.y);
                o[d4 * 4 + 2] = fmaf(o[d4 * 4 + 2], c, p * vv.z);
                o[d4 * 4 + 3] = fmaf(o[d4 * 4 + 3], c, p * vv.w);
            }
            m = mn;
        }
    }
    float inv = 1.f / l;
    float4* op = (float4*)(O + (b * SEQ + q) * DD + h * DH);
#pragma unroll
    for (int d4 = 0; d4 < 16; d4++) {
        float4 v;
        v.x = o[d4 * 4 + 0] * inv; v.y = o[d4 * 4 + 1] * inv;
        v.z = o[d4 * 4 + 2] * inv; v.w = o[d4 * 4 + 3] * inv;
        op[d4] = v;
    }
}

// ---------------- 9) layernorm (optional residual), row = one block ----------------
__global__ void k_ln(const float* __restrict__ X, const float* __restrict__ R,
                     const float* __restrict__ s, const float* __restrict__ bb,
                     float* __restrict__ Y, int hasRes) {
    int row = blockIdx.x;
    int t = threadIdx.x;
    __shared__ float red[256];
    float x = X[row * DD + t];
    if (hasRes) x += R[row * DD + t];
    red[t] = x;
    __syncthreads();
    for (int sdt = 128; sdt > 0; sdt >>= 1) {
        if (t < sdt) red[t] += red[t + sdt];
        __syncthreads();
    }
    float mean = red[0] * (1.0f / DD);
    __syncthreads();
    float d = x - mean;
    red[t] = d * d;
    __syncthreads();
    for (int sdt = 128; sdt > 0; sdt >>= 1) {
        if (t < sdt) red[t] += red[t + sdt];
        __syncthreads();
    }
    float var = red[0] * (1.0f / DD);
    Y[row * DD + t] = d * rsqrtf(var + 1e-5f) * s[t] + bb[t];
}

// ---------------- 10) logits = H @ w2 + b2 (one warp per token) ----------------
__global__ void k_logits(const float* __restrict__ H, const float* __restrict__ w2,
                         const float* __restrict__ b2) {
    int warp = threadIdx.x >> 5, lane = threadIdx.x & 31;
    int n = blockIdx.x * 8 + warp;
    float ssum = 0.f;
    for (int i = lane; i < DD; i += 32) ssum = fmaf(H[n * DD + i], w2[i], ssum);
#pragma unroll
    for (int off = 16; off; off >>= 1) ssum += __shfl_down_sync(0xffffffff, ssum, off);
    if (lane == 0) g_logits[n] = ssum + b2[0];
}

// ---------------- 11) dec: paint 4x4 dec_w per token -> patch_logits ----------------
__global__ void k_dec(const float* __restrict__ dec_w, const float* __restrict__ dec_b,
                      float* __restrict__ out_plog) {
    int bk = blockIdx.x;            // 0..255
    int b = bk >> 4, k = bk & 15;
    int t = threadIdx.x;            // pixel
    int y = t >> 4, x = t & 15;
    int i = y >> 2, a = y & 3, j = x >> 2, c = x & 3;
    float v = g_logits[b * SEQ + k * 16 + i * 4 + j] * __ldg(&dec_w[a * 4 + c]) + dec_b[0];
    out_plog[bk * 256 + t] = v;
}

// ---------------- 12) final assembly ----------------
__global__ void k_final(const float* __restrict__ plog, float* __restrict__ out_final) {
    int idx = blockIdx.x * blockDim.x + threadIdx.x;   // B*1024*1024
    int b = idx >> 20;
    int y = (idx >> 10) & 1023;
    int x = idx & 1023;
    int p = (y >> 4) * NW_ + (x >> 4);
    int k = g_map[b * NPATCH + p];
    float v = 0.f;
    if (k >= 0) v = plog[(b * 16 + k) * 256 + (y & 15) * 16 + (x & 15)];
    out_final[idx] = v;
}

// ---------------- launch ----------------
extern "C" void kernel_launch(void* const* d_in, const int* in_sizes, int n_in,
                              void* d_out, int out_size) {
    const float* image     = (const float*)d_in[0];
    const float* labels    = (const float*)d_in[1];
    const float* pe_w      = (const float*)d_in[2];
    const float* pe_b      = (const float*)d_in[3];
    const float* pos_embed = (const float*)d_in[4];
    const float* in_proj_w = (const float*)d_in[5];
    const float* in_proj_b = (const float*)d_in[6];
    const float* out_w     = (const float*)d_in[7];
    const float* out_b     = (const float*)d_in[8];
    const float* ln1_s     = (const float*)d_in[9];
    const float* ln1_b     = (const float*)d_in[10];
    const float* ff1_w     = (const float*)d_in[11];
    const float* ff1_b     = (const float*)d_in[12];
    const float* ff2_w     = (const float*)d_in[13];
    const float* ff2_b     = (const float*)d_in[14];
    const float* ln2_s     = (const float*)d_in[15];
    const float* ln2_b     = (const float*)d_in[16];
    const float* head_ln_s = (const float*)d_in[17];
    const float* head_ln_b = (const float*)d_in[18];
    const float* head_w1   = (const float*)d_in[19];
    const float* head_b1   = (const float*)d_in[20];
    const float* head_w2   = (const float*)d_in[21];
    const float* head_b2   = (const float*)d_in[22];
    const float* dec_w     = (const float*)d_in[23];
    const float* dec_b     = (const float*)d_in[24];

    float* out = (float*)d_out;
    float* out_coarse = out + OFF_COARSE;
    float* out_patch  = out + OFF_PATCH;
    float* out_plab   = out + OFF_PLAB;
    float* out_coord  = out + OFF_COORD;
    float* out_plog   = out + OFF_PLOG;
    float* out_final  = out + OFF_FINAL;

    // device scratch pointers
    float *pX, *pQKV, *pT1, *pT2;
    cudaGetSymbolAddress((void**)&pX,   g_X);
    cudaGetSymbolAddress((void**)&pQKV, g_QKV);
    cudaGetSymbolAddress((void**)&pT1,  g_T1);
    cudaGetSymbolAddress((void**)&pT2,  g_T2);

    // global branch
    k_coarse <<< (BB * 256 * 256) / 256, 256 >>> (labels, out_coarse);
    k_scores <<< (BB * NPATCH) / 256, 256 >>> (out_coarse);
    k_mapinit<<< (BB * NPATCH + 255) / 256, 256 >>> ();
    k_topk   <<< BB, 256 >>> ();
    k_gather <<< BB * KK, 256 >>> (image, labels, out_patch, out_plab, out_coord);

    // local branch: tokens
    k_embed  <<< NTOK, 256 >>> (out_patch, pe_w, pe_b, pos_embed);

    for (int l = 0; l < NL; l++) {
        // qkv
        k_sgemm <<< dim3(3 * DD / 64, NTOK / 64), 256 >>> (
            pX, in_proj_w + l * 3 * DD * DD, in_proj_b + l * 3 * DD, pQKV,
            NTOK, 3 * DD, DD, 0);
        // attention
        k_attn <<< BB * NH, 256 >>> (pQKV, pT2);
        // out proj -> T1 (used as [NTOK,DD])
        k_sgemm <<< dim3(DD / 64, NTOK / 64), 256 >>> (
            pT2, out_w + l * DD * DD, out_b + l * DD, pT1,
            NTOK, DD, DD, 0);
        // X = LN(X + proj)
        k_ln <<< NTOK, 256 >>> (pX, pT1, ln1_s + l * DD, ln1_b + l * DD, pX, 1);
        // ff1 + gelu
        k_sgemm <<< dim3(DFF / 64, NTOK / 64), 256 >>> (
            pX, ff1_w + l * DFF * DD, ff1_b + l * DFF, pT1,
            NTOK, DFF, DD, 1);
        // ff2
        k_sgemm <<< dim3(DD / 64, NTOK / 64), 256 >>> (
            pT1, ff2_w + l * DD * DFF, ff2_b + l * DD, pT2,
            NTOK, DD, DFF, 0);
        // X = LN(X + ff)
        k_ln <<< NTOK, 256 >>> (pX, pT2, ln2_s + l * DD, ln2_b + l * DD, pX, 1);
    }

    // head
    k_ln <<< NTOK, 256 >>> (pX, nullptr, head_ln_s, head_ln_b, pT2, 0);
    k_sgemm <<< dim3(DD / 64, NTOK / 64), 256 >>> (
        pT2, head_w1, head_b1, pT1, NTOK, DD, DD, 1);
    k_logits <<< NTOK / 8, 256 >>> (pT1, head_w2, head_b2);

    // decode + assemble
    k_dec   <<< BB * KK, 256 >>> (dec_w, dec_b, out_plog);
    k_final <<< (BB * HH * WW) / 256, 256 >>> (out_plog, out_final);
}

// round 11
// speedup vs baseline: 1.0031x; 1.0012x over previous
#include <cuda_runtime.h>
#include <cuda_bf16.h>
#include <math.h>

// ---------------- constants ----------------
#define BB 16          // batch
#define HH 1024
#define WW 1024
#define PS 16
#define IPS 4
#define CS 4
#define KK 16          // top-k patches
#define DD 256         // model dim
#define NH 4
#define DH 64
#define DFF 1024
#define NL 2
#define NW_ 64         // patches per row = 1024/16
#define NPATCH 4096    // 64*64
#define SEQ 256        // tokens per batch = K*16
#define NTOK 4096      // B*SEQ

// output layout (f32 element offsets, tuple concatenated flat)
#define LEN_COARSE (BB*256*256)              // 1048576
#define OFF_COARSE 0
#define OFF_PATCH  (OFF_COARSE + LEN_COARSE)
#define LEN_PATCH  (BB*KK*PS*PS)             // 65536
#define OFF_PLAB   (OFF_PATCH + LEN_PATCH)
#define OFF_COORD  (OFF_PLAB + LEN_PATCH)
#define LEN_COORD  (BB*KK*2)                 // 512
#define OFF_PLOG   (OFF_COORD + LEN_COORD)
#define OFF_FINAL  (OFF_PLOG + LEN_PATCH)

// ---------------- scratch (static device globals; no allocation) ----------------
__device__ float g_scores[BB * NPATCH];
__device__ int   g_idx[BB * KK];
__device__ int   g_map[BB * NPATCH];
__device__ float g_X   [NTOK * DD];      // tokens
__device__ float g_QKV [NTOK * 3 * DD];  // qkv
__device__ float g_T1  [NTOK * DFF];     // ff hidden / proj / head gelu
__device__ float g_T2  [NTOK * DD];      // attn concat / ff out / head ln
__device__ float g_logits[NTOK];

__device__ __forceinline__ float gelu_exact(float v) {
    return 0.5f * v * (1.0f + erff(v * 0.70710678118654752f));
}

// ---------------- 1) coarse = avgpool4x4(labels) -> out ----------------
__global__ void k_coarse(const float* __restrict__ labels, float* __restrict__ out_coarse) {
    int idx = blockIdx.x * blockDim.x + threadIdx.x;   // B*256*256
    int b  = idx >> 16;
    int yc = (idx >> 8) & 255;
    int xc = idx & 255;
    const float* lp = labels + b * (HH * WW) + (yc * 4) * WW + xc * 4;
    float s = 0.f;
#pragma unroll
    for (int dy = 0; dy < 4; dy++)
#pragma unroll
        for (int dx = 0; dx < 4; dx++) s += lp[dy * WW + dx];
    out_coarse[idx] = s * 0.0625f;
}

// ---------------- 2) per-patch score = avgpool4x4(coarse) ----------------
__global__ void k_scores(const float* __restrict__ coarse) {
    int idx = blockIdx.x * blockDim.x + threadIdx.x;   // B*4096
    int b = idx >> 12;
    int p = idx & 4095;
    int hi = p >> 6, wi = p & 63;
    const float* cp = coarse + b * 65536 + (hi * 4) * 256 + wi * 4;
    float s = 0.f;
#pragma unroll
    for (int dy = 0; dy < 4; dy++)
#pragma unroll
        for (int dx = 0; dx < 4; dx++) s += cp[dy * 256 + dx];
    g_scores[idx] = s * 0.0625f;
}

// ---------------- 3) map init ----------------
__global__ void k_mapinit() {
    int idx = blockIdx.x * blockDim.x + threadIdx.x;
    if (idx < BB * NPATCH) g_map[idx] = -1;
}

// ---------------- 4) top-K per batch (descending, lower index on ties) ----------------
__global__ void k_topk() {
    int b = blockIdx.x;
    __shared__ float sv[NPATCH];
    __shared__ float rv[256];
    __shared__ int   ri[256];
    for (int i = threadIdx.x; i < NPATCH; i += 256) sv[i] = g_scores[b * NPATCH + i];
    __syncthreads();
    for (int it = 0; it < KK; it++) {
        float best = -3.0e38f; int bi = NPATCH;
        for (int i = threadIdx.x; i < NPATCH; i += 256) {
            float v = sv[i];
            if (v > best) { best = v; bi = i; }   // ascending scan keeps lowest idx on ties
        }
        rv[threadIdx.x] = best; ri[threadIdx.x] = bi;
        __syncthreads();
        for (int s = 128; s > 0; s >>= 1) {
            if (threadIdx.x < s) {
                float v2 = rv[threadIdx.x + s]; int i2 = ri[threadIdx.x + s];
                if (v2 > rv[threadIdx.x] || (v2 == rv[threadIdx.x] && i2 < ri[threadIdx.x])) {
                    rv[threadIdx.x] = v2; ri[threadIdx.x] = i2;
                }
            }
            __syncthreads();
        }
        if (threadIdx.x == 0) { g_idx[b * KK + it] = ri[0]; sv[ri[0]] = -3.0e38f; }
        __syncthreads();
    }
}

// ---------------- 5) gather patches / labels / coords / map ----------------
__global__ void k_gather(const float* __restrict__ image, const float* __restrict__ labels,
                         float* __restrict__ out_p, float* __restrict__ out_l,
                         float* __restrict__ out_c) {
    int bk = blockIdx.x;            // 0..255
    int b = bk >> 4, k = bk & 15;
    int pidx = g_idx[bk];
    int hi = pidx >> 6, wi = pidx & 63;
    int t = threadIdx.x;
    int py = t >> 4, px = t & 15;
    int base = b * (HH * WW) + (hi * 16 + py) * WW + wi * 16 + px;
    out_p[bk * 256 + t] = image[base];
    out_l[bk * 256 + t] = labels[base];
    if (t == 0) {
        out_c[bk * 2 + 0] = (float)(hi * 16);
        out_c[bk * 2 + 1] = (float)(wi * 16);
        g_map[b * NPATCH + pidx] = k;
    }
}

// ---------------- 6) patch embed: tokens = conv4x4(pe_w) + pe_b + pos ----------------
__global__ void k_embed(const float* __restrict__ patches, const float* __restrict__ pe_w,
                        const float* __restrict__ pe_b, const float* __restrict__ pos) {
    int n = blockIdx.x;             // token 0..4095
    int d = threadIdx.x;            // 0..255
    int r = n & 255;
    int b = n >> 8;
    int k = r >> 4, q = r & 15;
    int i = q >> 2, j = q & 3;
    __shared__ float sub[16];
    if (d < 16) {
        int a = d >> 2, bb = d & 3;
        sub[d] = patches[(b * 16 + k) * 256 + (i * 4 + a) * 16 + (j * 4 + bb)];
    }
    __syncthreads();
    float s = pe_b[d] + pos[q * DD + d];
#pragma unroll
    for (int p = 0; p < 16; p++) s += __ldg(&pe_w[d * 16 + p]) * sub[p];
    g_X[n * DD + d] = s;
}

// ---------------- 7) SGEMM: C[M,N] = act(A[M,K] * W[N,K]^T + bias) ----------------
// 64x64 tile, BK=16, 256 threads, 4x4 per thread
__global__ __launch_bounds__(256) void k_sgemm(const float* __restrict__ A,
                                               const float* __restrict__ W,
                                               const float* __restrict__ bias,
                                               float* __restrict__ C,
                                               int M, int N, int Kd, int act) {
    __shared__ float As[16][68];
    __shared__ float Bs[16][68];
    int n0 = blockIdx.x * 64;
    int m0 = blockIdx.y * 64;
    int t = threadIdx.x;
    int tx = t & 15, ty = t >> 4;
    int lrow = t >> 2;
    int lk = (t & 3) * 4;
    float acc[4][4];
#pragma unroll
    for (int i = 0; i < 4; i++)
#pragma unroll
        for (int j = 0; j < 4; j++) acc[i][j] = 0.f;

    const float* Ap = A + (m0 + lrow) * Kd + lk;
    const float* Wp = W + (n0 + lrow) * Kd + lk;

    for (int k0 = 0; k0 < Kd; k0 += 16) {
        float4 a4 = *(const float4*)(Ap + k0);
        float4 b4 = *(const float4*)(Wp + k0);
        __syncthreads();
        As[lk + 0][lrow] = a4.x; As[lk + 1][lrow] = a4.y;
        As[lk + 2][lrow] = a4.z; As[lk + 3][lrow] = a4.w;
        Bs[lk + 0][lrow] = b4.x; Bs[lk + 1][lrow] = b4.y;
        Bs[lk + 2][lrow] = b4.z; Bs[lk + 3][lrow] = b4.w;
        __syncthreads();
#pragma unroll
        for (int kk = 0; kk < 16; kk++) {
            float4 av = *(const float4*)&As[kk][ty * 4];
            float4 bv = *(const float4*)&Bs[kk][tx * 4];
            float ar[4] = {av.x, av.y, av.z, av.w};
            float br[4] = {bv.x, bv.y, bv.z, bv.w};
#pragma unroll
            for (int i = 0; i < 4; i++)
#pragma unroll
                for (int j = 0; j < 4; j++) acc[i][j] = fmaf(ar[i], br[j], acc[i][j]);
        }
    }
#pragma unroll
    for (int i = 0; i < 4; i++) {
        int m = m0 + ty * 4 + i;
#pragma unroll
        for (int j = 0; j < 4; j++) {
            int n = n0 + tx * 4 + j;
            float v = acc[i][j] + bias[n];
            if (act) v = gelu_exact(v);
            C[m * N + n] = v;
        }
    }
}

// ---------------- 8) attention: one block per (b,h), flash-style ----------------
__global__ __launch_bounds__(256, 1) void k_attn(const float* __restrict__ QKV,
                                                 float* __restrict__ O) {
    int b = blockIdx.x >> 2;
    int h = blockIdx.x & 3;
    __shared__ float Ks[64 * 64];
    __shared__ float Vs[64 * 64];
    int q = threadIdx.x;            // query token 0..255

    float qreg[64];
    {
        const float4* qp = (const float4*)(QKV + ((b * SEQ + q) * 3 * DD) + h * DH);
#pragma unroll
        for (int d4 = 0; d4 < 16; d4++) {
            float4 v = qp[d4];
            qreg[d4 * 4 + 0] = v.x * 0.125f;
            qreg[d4 * 4 + 1] = v.y * 0.125f;
            qreg[d4 * 4 + 2] = v.z * 0.125f;
            qreg[d4 * 4 + 3] = v.w * 0.125f;
        }
    }
    float o[64];
#pragma unroll
    for (int d = 0; d < 64; d++) o[d] = 0.f;
    float m = -3.0e38f, l = 0.f;

    for (int tile = 0; tile < 4; tile++) {
        __syncthreads();
        for (int i = threadIdx.x; i < 4096; i += 256) {
            int tok = i >> 6, d = i & 63;
            int gbase = (b * SEQ + tile * 64 + tok) * 3 * DD + h * DH + d;
            Ks[i] = QKV[gbase + DD];
            Vs[i] = QKV[gbase + 2 * DD];
        }
        __syncthreads();
#pragma unroll 2
        for (int j = 0; j < 64; j++) {
            const float4* kp = (const float4*)&Ks[j * 64];
            float s = 0.f;
#pragma unroll
            for (int d4 = 0; d4 < 16; d4++) {
                float4 kv = kp[d4];
                s = fmaf(qreg[d4 * 4 + 0], kv.x, s);
                s = fmaf(qreg[d4 * 4 + 1], kv.y, s);
                s = fmaf(qreg[d4 * 4 + 2], kv.z, s);
                s = fmaf(qreg[d4 * 4 + 3], kv.w, s);
            }
            float mn = fmaxf(m, s);
            float c = expf(m - mn);
            float p = expf(s - mn);
            l = l * c + p;
            const float4* vp = (const float4*)&Vs[j * 64];
#pragma unroll
            for (int d4 = 0; d4 < 16; d4++) {
                float4 vv = vp[d4];
                o[d4 * 4 + 0] = fmaf(o[d4 * 4 + 0], c, p * vv.x);
                o[d4 * 4 + 1] = fmaf(o[d4 * 4 + 1], c, p * vv.y);
                o[d4 * 4 + 2] = fmaf(o[d4 * 4 + 2], c, p * vv.z);
                o[d4 * 4 + 3] = fmaf(o[d4 * 4 + 3], c, p * vv.w);
            }
            m = mn;
        }
    }
    float inv = 1.f / l;
    float4* op = (float4*)(O + (b * SEQ + q) * DD + h * DH);
#pragma unroll
    for (int d4 = 0; d4 < 16; d4++) {
        float4 v;
        v.x = o[d4 * 4 + 0] * inv; v.y = o[d4 * 4 + 1] * inv;
        v.z = o[d4 * 4 + 2] * inv; v.w = o[d4 * 4 + 3] * inv;
        op[d4] = v;
    }
}

// ---------------- 9) layernorm (optional residual), row = one block ----------------
__global__ void k_ln(const float* __restrict__ X, const float* __restrict__ R,
                     const float* __restrict__ s, const float* __restrict__ bb,
                     float* __restrict__ Y, int hasRes) {
    int row = blockIdx.x;
    int t = threadIdx.x;
    __shared__ float red[256];
    float x = X[row * DD + t];
    if (hasRes) x += R[row * DD + t];
    red[t] = x;
    __syncthreads();
    for (int sdt = 128; sdt > 0; sdt >>= 1) {
        if (t < sdt) red[t] += red[t + sdt];
        __syncthreads();
    }
    float mean = red[0] * (1.0f / DD);
    __syncthreads();
    float d = x - mean;
    red[t] = d * d;
    __syncthreads();
    for (int sdt = 128; sdt > 0; sdt >>= 1) {
        if (t < sdt) red[t] += red[t + sdt];
        __syncthreads();
    }
    float var = red[0] * (1.0f / DD);
    Y[row * DD + t] = d * rsqrtf(var + 1e-5f) * s[t] + bb[t];
}

// ---------------- 10) logits = H @ w2 + b2 (one warp per token) ----------------
__global__ void k_logits(const float* __restrict__ H, const float* __restrict__ w2,
                         const float* __restrict__ b2) {
    int warp = threadIdx.x >> 5, lane = threadIdx.x & 31;
    int n = blockIdx.x * 8 + warp;
    float ssum = 0.f;
    for (int i = lane; i < DD; i += 32) ssum = fmaf(H[n * DD + i], w2[i], ssum);
#pragma unroll
    for (int off = 16; off; off >>= 1) ssum += __shfl_down_sync(0xffffffff, ssum, off);
    if (lane == 0) g_logits[n] = ssum + b2[0];
}

// ---------------- 11) dec: paint 4x4 dec_w per token -> patch_logits ----------------
__global__ void k_dec(const float* __restrict__ dec_w, const float* __restrict__ dec_b,
                      float* __restrict__ out_plog) {
    int bk = blockIdx.x;            // 0..255
    int b = bk >> 4, k = bk & 15;
    int t = threadIdx.x;            // pixel
    int y = t >> 4, x = t & 15;
    int i = y >> 2, a = y & 3, j = x >> 2, c = x & 3;
    float v = g_logits[b * SEQ + k * 16 + i * 4 + j] * __ldg(&dec_w[a * 4 + c]) + dec_b[0];
    out_plog[bk * 256 + t] = v;
}

// ---------------- 12) final assembly ----------------
__global__ void k_final(const float* __restrict__ plog, float* __restrict__ out_final) {
    int idx = blockIdx.x * blockDim.x + threadIdx.x;   // B*1024*1024
    int b = idx >> 20;
    int y = (idx >> 10) & 1023;
    int x = idx & 1023;
    int p = (y >> 4) * NW_ + (x >> 4);
    int k = g_map[b * NPATCH + p];
    float v = 0.f;
    if (k >= 0) v = plog[(b * 16 + k) * 256 + (y & 15) * 16 + (x & 15)];
    out_final[idx] = v;
}

// ---------------- launch ----------------
extern "C" void kernel_launch(void* const* d_in, const int* in_sizes, int n_in,
                              void* d_out, int out_size) {
    const float* image     = (const float*)d_in[0];
    const float* labels    = (const float*)d_in[1];
    const float* pe_w      = (const float*)d_in[2];
    const float* pe_b      = (const float*)d_in[3];
    const float* pos_embed = (const float*)d_in[4];
    const float* in_proj_w = (const float*)d_in[5];
    const float* in_proj_b = (const float*)d_in[6];
    const float* out_w     = (const float*)d_in[7];
    const float* out_b     = (const float*)d_in[8];
    const float* ln1_s     = (const float*)d_in[9];
    const float* ln1_b     = (const float*)d_in[10];
    const float* ff1_w     = (const float*)d_in[11];
    const float* ff1_b     = (const float*)d_in[12];
    const float* ff2_w     = (const float*)d_in[13];
    const float* ff2_b     = (const float*)d_in[14];
    const float* ln2_s     = (const float*)d_in[15];
    const float* ln2_b     = (const float*)d_in[16];
    const float* head_ln_s = (const float*)d_in[17];
    const float* head_ln_b = (const float*)d_in[18];
    const float* head_w1   = (const float*)d_in[19];
    const float* head_b1   = (const float*)d_in[20];
    const float* head_w2   = (const float*)d_in[21];
    const float* head_b2   = (const float*)d_in[22];
    const float* dec_w     = (const float*)d_in[23];
    const float* dec_b     = (const float*)d_in[24];

    float* out = (float*)d_out;
    float* out_coarse = out + OFF_COARSE;
    float* out_patch  = out + OFF_PATCH;
    float* out_plab   = out + OFF_PLAB;
    float* out_coord  = out + OFF_COORD;
    float* out_plog   = out + OFF_PLOG;
    float* out_final  = out + OFF_FINAL;

    // device scratch pointers
    float *pX, *pQKV, *pT1, *pT2;
    cudaGetSymbolAddress((void**)&pX,   g_X);
    cudaGetSymbolAddress((void**)&pQKV, g_QKV);
    cudaGetSymbolAddress((void**)&pT1,  g_T1);
    cudaGetSymbolAddress((void**)&pT2,  g_T2);

    // global branch
    k_coarse <<< (BB * 256 * 256) / 256, 256 >>> (labels, out_coarse);
    k_scores <<< (BB * NPATCH) / 256, 256 >>> (out_coarse);
    k_mapinit<<< (BB * NPATCH + 255) / 256, 256 >>> ();
    k_topk   <<< BB, 256 >>> ();
    k_gather <<< BB * KK, 256 >>> (image, labels, out_patch, out_plab, out_coord);

    // local branch: tokens
    k_embed  <<< NTOK, 256 >>> (out_patch, pe_w, pe_b, pos_embed);

    for (int l = 0; l < NL; l++) {
        // qkv
        k_sgemm <<< dim3(3 * DD / 64, NTOK / 64), 256 >>> (
            pX, in_proj_w + l * 3 * DD * DD, in_proj_b + l * 3 * DD, pQKV,
            NTOK, 3 * DD, DD, 0);
        // attention
        k_attn <<< BB * NH, 256 >>> (pQKV, pT2);
        // out proj -> T1 (used as [NTOK,DD])
        k_sgemm <<< dim3(DD / 64, NTOK / 64), 256 >>> (
            pT2, out_w + l * DD * DD, out_b + l * DD, pT1,
            NTOK, DD, DD, 0);
        // X = LN(X + proj)
        k_ln <<< NTOK, 256 >>> (pX, pT1, ln1_s + l * DD, ln1_b + l * DD, pX, 1);
        // ff1 + gelu
        k_sgemm <<< dim3(DFF / 64, NTOK / 64), 256 >>> (
            pX, ff1_w + l * DFF * DD, ff1_b + l * DFF, pT1,
            NTOK, DFF, DD, 1);
        // ff2
        k_sgemm <<< dim3(DD / 64, NTOK / 64), 256 >>> (
            pT1, ff2_w + l * DD * DFF, ff2_b + l * DD, pT2,
            NTOK, DD, DFF, 0);
        // X = LN(X + ff)
        k_ln <<< NTOK, 256 >>> (pX, pT2, ln2_s + l * DD, ln2_b + l * DD, pX, 1);
    }

    // head
    k_ln <<< NTOK, 256 >>> (pX, nullptr, head_ln_s, head_ln_b, pT2, 0);
    k_sgemm <<< dim3(DD / 64, NTOK / 64), 256 >>> (
        pT2, head_w1, head_b1, pT1, NTOK, DD, DD, 1);
    k_logits <<< NTOK / 8, 256 >>> (pT1, head_w2, head_b2);

    // decode + assemble
    k_dec   <<< BB * KK, 256 >>> (dec_w, dec_b, out_plog);
    k_final <<< (BB * HH * WW) / 256, 256 >>> (out_plog, out_final);
}